// round 7
// baseline (speedup 1.0000x reference)
#include <cuda_runtime.h>
#include <cstdint>

#define B_   256
#define T_   512
#define DIN  128
#define H_   512
#define DOUT 64

#define CSZ         8
#define NSTAGE      3
#define CHUNK_K     32
#define CHUNK_BYTES (CHUNK_K * H_ * 4)     // 65536
#define NCHUNK      (H_ / CHUNK_K)         // 16 chunks per step
#define TOTAL_CI    (T_ * NCHUNK)          // 8192

// smem layout (dynamic)
#define SM_W     0
#define SM_HD    (NSTAGE * CHUNK_BYTES)        // 196608 : h dup {h,h} [2][512] float2
#define SM_RED   (SM_HD + 2 * H_ * 8)          // 204800 : reduction scratch 256*16B
#define SM_BAR   (SM_RED + 4096)               // 208896 : full[3] @+0, empty[3] @+24
#define SM_TOTAL (SM_BAR + 64)                 // 208960

// Scratch (allocation-free rule: __device__ globals)
__device__ float g_xproj[(size_t)B_ * T_ * H_];  // [b][t][h] = inputs@Win + brec
__device__ float g_hall [(size_t)B_ * T_ * H_];  // [b][t][h] = h_t for all t

// Packed fp32x2 FMA
union F2U { float2 f; unsigned long long u; };
__device__ __forceinline__ float2 ffma2(float2 a, float2 b, float2 c) {
    F2U A, Bv, C, D;
    A.f = a; Bv.f = b; C.f = c;
    asm("fma.rn.f32x2 %0, %1, %2, %3;" : "=l"(D.u) : "l"(A.u), "l"(Bv.u), "l"(C.u));
    return D.f;
}

__device__ __forceinline__ uint32_t s2u(const void* p) {
    uint32_t a;
    asm("{ .reg .u64 t; cvta.to.shared.u64 t, %1; cvt.u32.u64 %0, t; }" : "=r"(a) : "l"(p));
    return a;
}
__device__ __forceinline__ void mb_init(uint32_t a, uint32_t cnt) {
    asm volatile("mbarrier.init.shared.b64 [%0], %1;" :: "r"(a), "r"(cnt) : "memory");
}
__device__ __forceinline__ void mb_expect(uint32_t a, uint32_t bytes) {
    asm volatile("mbarrier.arrive.expect_tx.shared.b64 _, [%0], %1;" :: "r"(a), "r"(bytes) : "memory");
}
// Remote arrive with cluster-scope RELEASE: orders the preceding local
// expect_tx before the producer can observe this arrival. (R3 bug: default
// .cta semantics gave no cross-CTA ordering -> tx-before-expect underflow.)
__device__ __forceinline__ void mb_arrive_remote_rel(uint32_t a, uint32_t rank) {
    asm volatile("{ .reg .b32 r; mapa.shared::cluster.u32 r, %0, %1;"
                 "  mbarrier.arrive.release.cluster.shared::cluster.b64 _, [r]; }"
                 :: "r"(a), "r"(rank) : "memory");
}
// local-scope wait (full barriers: tx completion is local)
__device__ __forceinline__ void mb_wait_cta(uint32_t a, uint32_t ph) {
    uint32_t done;
    asm volatile("{ .reg .pred p; mbarrier.try_wait.parity.acquire.cta.shared::cta.b64 p, [%1], %2;"
                 "  selp.b32 %0, 1, 0, p; }" : "=r"(done) : "r"(a), "r"(ph) : "memory");
    if (!done) {
        asm volatile("{ .reg .pred P;\n"
                     "WL_%=: mbarrier.try_wait.parity.acquire.cta.shared::cta.b64 P, [%0], %1, 0x989680;\n"
                     " @P bra WD_%=;\n bra WL_%=;\nWD_%=: }" :: "r"(a), "r"(ph) : "memory");
    }
}
// cluster-scope acquire wait (empty barriers: must sync-with remote releases)
__device__ __forceinline__ void mb_wait_cluster(uint32_t a, uint32_t ph) {
    uint32_t done;
    asm volatile("{ .reg .pred p; mbarrier.try_wait.parity.acquire.cluster.shared::cta.b64 p, [%1], %2;"
                 "  selp.b32 %0, 1, 0, p; }" : "=r"(done) : "r"(a), "r"(ph) : "memory");
    if (!done) {
        asm volatile("{ .reg .pred P;\n"
                     "WL_%=: mbarrier.try_wait.parity.acquire.cluster.shared::cta.b64 P, [%0], %1, 0x989680;\n"
                     " @P bra WD_%=;\n bra WL_%=;\nWD_%=: }" :: "r"(a), "r"(ph) : "memory");
    }
}
__device__ __forceinline__ void bulk_mc(uint32_t dst, const void* src, uint32_t bytes,
                                        uint32_t mbar, uint16_t mask) {
    asm volatile("cp.async.bulk.shared::cluster.global.mbarrier::complete_tx::bytes.multicast::cluster"
                 " [%0], [%1], %2, [%3], %4;"
                 :: "r"(dst), "l"(src), "r"(bytes), "r"(mbar), "h"(mask) : "memory");
}

// ---------------------------------------------------------------------------
// Kernel A: xproj = inputs @ Win + brec   (measured 580us)
// ---------------------------------------------------------------------------
__global__ void __launch_bounds__(256) rnn_xproj(
    const float* __restrict__ inputs,
    const float* __restrict__ Win,
    const float* __restrict__ brec)
{
    __shared__ __align__(16) float2 x_dup[16][DIN];
    const int tid = threadIdx.x;
    const size_t r0 = (size_t)blockIdx.x * 16;

    for (int i = tid; i < 16 * DIN; i += 256) {
        int r = i >> 7, k = i & (DIN - 1);
        float v = inputs[(r0 + r) * DIN + k];
        x_dup[r][k] = make_float2(v, v);
    }
    __syncthreads();

    const float2* __restrict__ W2 = reinterpret_cast<const float2*>(Win);
    float2 acc[16];
#pragma unroll
    for (int r = 0; r < 16; r++) acc[r] = make_float2(0.f, 0.f);

#pragma unroll 2
    for (int k = 0; k < DIN; k += 2) {
        float2 w0 = W2[(size_t)k * (H_ / 2) + tid];
        float2 w1 = W2[(size_t)(k + 1) * (H_ / 2) + tid];
#pragma unroll
        for (int r = 0; r < 16; r++) {
            float4 hx = *reinterpret_cast<const float4*>(&x_dup[r][k]);
            acc[r] = ffma2(make_float2(hx.x, hx.y), w0, acc[r]);
            acc[r] = ffma2(make_float2(hx.z, hx.w), w1, acc[r]);
        }
    }

    float2 bb = reinterpret_cast<const float2*>(brec)[tid];
    float2* __restrict__ out2 = reinterpret_cast<float2*>(g_xproj);
#pragma unroll
    for (int r = 0; r < 16; r++)
        out2[(r0 + r) * (H_ / 2) + tid] = make_float2(acc[r].x + bb.x, acc[r].y + bb.y);
}

// ---------------------------------------------------------------------------
// Kernel B: recurrence. Batch-parallel (2 rows/CTA, 128 CTAs, no h exchange).
// Wrec streamed via 3-stage rotating-producer multicast pipeline per cluster.
// full[st]: count 1 (local expect_tx) + 64KB tx. empty[st]: count 64
// (8 warps x 8 CTAs), arrivals carry .release.cluster.
// ---------------------------------------------------------------------------
extern __shared__ __align__(16) unsigned char sm[];

__global__ void __launch_bounds__(256, 1) __cluster_dims__(CSZ, 1, 1)
rnn_recurrent(const float* __restrict__ Wrec,
              const float* __restrict__ h0)
{
    const int tid  = threadIdx.x;
    const int warp = tid >> 5, lane = tid & 31;
    const int p    = warp >> 2;                // 0..1 (k-parity / finalize row)
    const int q    = (warp & 3) * 32 + lane;   // 0..127 (col quad)
    const int c0   = q * 4;
    uint32_t rank; asm("mov.u32 %0, %%cluster_ctarank;" : "=r"(rank));
    const int b0 = blockIdx.x * 2;

    const uint32_t smb    = s2u(sm);
    const uint32_t fullb  = smb + SM_BAR;
    const uint32_t emptyb = smb + SM_BAR + 24;

    float2* hd  = reinterpret_cast<float2*>(sm + SM_HD);   // [2][512] {h,h}
    float4* red = reinterpret_cast<float4*>(sm + SM_RED);  // [256]

    if (tid == 0)
        for (int st = 0; st < 3; st++) { mb_init(fullb + 8*st, 1); mb_init(emptyb + 8*st, 64); }

    for (int i = tid; i < H_; i += 256) {      // h = h0 for both rows (dup)
        float v = h0[i];
        float2 vv = make_float2(v, v);
        hd[i] = vv; hd[H_ + i] = vv;
    }
    __syncthreads();

    // Arm all three full barriers BEFORE any producer can issue.
    if (tid == 0)
        for (int st = 0; st < 3; st++) mb_expect(fullb + 8*st, CHUNK_BYTES);
    __syncthreads();
    // Cluster barrier: every CTA's inits + expects are done before any TMA.
    asm volatile("barrier.cluster.arrive.aligned;" ::: "memory");
    asm volatile("barrier.cluster.wait.aligned;"   ::: "memory");

    // Prologue: chunks 0..2, no empty-wait (buffers trivially empty).
    if (tid == 0) {
        for (int nci = 0; nci < NSTAGE; nci++)
            if ((nci & 7) == (int)rank)
                bulk_mc(smb + SM_W + nci * CHUNK_BYTES,
                        Wrec + (size_t)nci * CHUNK_K * H_,
                        CHUNK_BYTES, fullb + 8*nci, 0xFF);
    }

    int pp[3]  = {0, 0, 0};                    // producer empty parity per stage
    int fph[3] = {0, 0, 0};                    // consumer full parity per stage
    float4 xpv = *reinterpret_cast<const float4*>(
        g_xproj + ((size_t)(b0 + p) * T_ + 0) * H_ + c0);

    float2 a00 = make_float2(0.f, 0.f), a01 = a00, a10 = a00, a11 = a00;

    int st = 0;
    for (int ci = 0; ci < TOTAL_CI; ci++) {
        if (lane == 0) mb_wait_cta(fullb + 8*st, fph[st]);
        fph[st] ^= 1;
        __syncwarp();

        const float4* wb  = reinterpret_cast<const float4*>(sm + SM_W + st * CHUNK_BYTES);
        const float4* h40 = reinterpret_cast<const float4*>(hd)      + (ci & 15) * (CHUNK_K / 2);
        const float4* h41 = reinterpret_cast<const float4*>(hd + H_) + (ci & 15) * (CHUNK_K / 2);
        int widx = (2 * p) * 128 + q;
#pragma unroll
        for (int j = 0; j < 8; j++) {
            float4 w0 = wb[widx];
            float4 w1 = wb[widx + 128];
            int hj = 2 * j + p;                 // {h[k],h[k],h[k+1],h[k+1]}
            float4 hA = h40[hj];
            float4 hB = h41[hj];
            a00 = ffma2(make_float2(hA.x, hA.y), make_float2(w0.x, w0.y), a00);
            a01 = ffma2(make_float2(hA.x, hA.y), make_float2(w0.z, w0.w), a01);
            a00 = ffma2(make_float2(hA.z, hA.w), make_float2(w1.x, w1.y), a00);
            a01 = ffma2(make_float2(hA.z, hA.w), make_float2(w1.z, w1.w), a01);
            a10 = ffma2(make_float2(hB.x, hB.y), make_float2(w0.x, w0.y), a10);
            a11 = ffma2(make_float2(hB.x, hB.y), make_float2(w0.z, w0.w), a11);
            a10 = ffma2(make_float2(hB.z, hB.w), make_float2(w1.x, w1.y), a10);
            a11 = ffma2(make_float2(hB.z, hB.w), make_float2(w1.z, w1.w), a11);
            widx += 512;
        }

        // Re-arm THIS stage's full barrier for delivery ci+3 (tid0), then
        // release-arrive the producer's empty barrier. tid0's arrive is
        // release-ordered after its expect -> producer can never deliver
        // into an un-expected barrier.
        if (tid == 0 && ci + NSTAGE < TOTAL_CI) mb_expect(fullb + 8*st, CHUNK_BYTES);
        if (lane == 0) mb_arrive_remote_rel(emptyb + 8*st, (uint32_t)((ci + NSTAGE) & 7));

        // Produce chunk ci+3 (same stage) if it's mine.
        if (tid == 0) {
            int nci = ci + NSTAGE;
            if (nci < TOTAL_CI && (nci & 7) == (int)rank) {
                mb_wait_cluster(emptyb + 8*st, pp[st]); pp[st] ^= 1;
                bulk_mc(smb + SM_W + st * CHUNK_BYTES,
                        Wrec + (size_t)(nci & 15) * CHUNK_K * H_,
                        CHUNK_BYTES, fullb + 8*st, 0xFF);
            }
        }

        if ((ci & 15) == 15) {                  // ---- step end ----
            int t = ci >> 4;
            red[tid] = p ? make_float4(a00.x, a00.y, a01.x, a01.y)
                         : make_float4(a10.x, a10.y, a11.x, a11.y);
            __syncthreads();
            float4 o = red[tid ^ 128];
            float2 m0 = p ? a10 : a00;
            float2 m1 = p ? a11 : a01;
            float v0 = tanhf(m0.x + o.x + xpv.x);
            float v1 = tanhf(m0.y + o.y + xpv.y);
            float v2 = tanhf(m1.x + o.z + xpv.z);
            float v3 = tanhf(m1.y + o.w + xpv.w);
            *reinterpret_cast<float4*>(
                g_hall + ((size_t)(b0 + p) * T_ + t) * H_ + c0) = make_float4(v0, v1, v2, v3);
            float4* hdst = reinterpret_cast<float4*>(hd + (size_t)p * H_ + c0);
            hdst[0] = make_float4(v0, v0, v1, v1);
            hdst[1] = make_float4(v2, v2, v3, v3);
            a00 = a01 = a10 = a11 = make_float2(0.f, 0.f);
            if (t + 1 < T_)
                xpv = *reinterpret_cast<const float4*>(
                    g_xproj + ((size_t)(b0 + p) * T_ + (t + 1)) * H_ + c0);
            __syncthreads();
        }

        st = (st == 2) ? 0 : st + 1;
    }

    // No CTA may exit while a peer's multicast/arrive targeting it is in flight.
    asm volatile("barrier.cluster.arrive.aligned;" ::: "memory");
    asm volatile("barrier.cluster.wait.aligned;"   ::: "memory");
}

// ---------------------------------------------------------------------------
// Kernel C: out = g_hall @ Wout + bout
// ---------------------------------------------------------------------------
__global__ void __launch_bounds__(256, 1) rnn_outproj(
    const float* __restrict__ Wout,
    const float* __restrict__ bout,
    float* __restrict__ out)
{
    __shared__ __align__(16) float2 hdq[64][64];
    const int tid = threadIdx.x;
    const int pair = tid & 31;
    const int rg = tid >> 5;
    const size_t r0 = (size_t)blockIdx.x * 64;

    float2 acc[8];
#pragma unroll
    for (int i = 0; i < 8; i++) acc[i] = make_float2(0.f, 0.f);

    const float2* __restrict__ Wo2 = reinterpret_cast<const float2*>(Wout);

    for (int kc = 0; kc < H_; kc += 64) {
        __syncthreads();
        for (int i = tid; i < 64 * 64; i += 256) {
            int r = i >> 6, k = i & 63;
            float v = g_hall[(r0 + r) * H_ + kc + k];
            hdq[r][k] = make_float2(v, v);
        }
        __syncthreads();

#pragma unroll 4
        for (int kk = 0; kk < 64; kk += 2) {
            float2 w0 = Wo2[(size_t)(kc + kk) * (DOUT / 2) + pair];
            float2 w1 = Wo2[(size_t)(kc + kk + 1) * (DOUT / 2) + pair];
#pragma unroll
            for (int i = 0; i < 8; i++) {
                int r = rg * 8 + i;
                float4 hx = *reinterpret_cast<const float4*>(&hdq[r][kk]);
                acc[i] = ffma2(make_float2(hx.x, hx.y), w0, acc[i]);
                acc[i] = ffma2(make_float2(hx.z, hx.w), w1, acc[i]);
            }
        }
    }

    float2 bb = reinterpret_cast<const float2*>(bout)[pair];
    float2* __restrict__ out2 = reinterpret_cast<float2*>(out);
#pragma unroll
    for (int i = 0; i < 8; i++) {
        int r = rg * 8 + i;
        out2[(r0 + r) * (DOUT / 2) + pair] =
            make_float2(acc[i].x + bb.x, acc[i].y + bb.y);
    }
}

// ---------------------------------------------------------------------------
extern "C" void kernel_launch(void* const* d_in, const int* in_sizes, int n_in,
                              void* d_out, int out_size)
{
    const float* inputs = (const float*)d_in[0];
    const float* Win    = (const float*)d_in[1];
    const float* Wrec   = (const float*)d_in[2];
    const float* brec   = (const float*)d_in[3];
    const float* Wout   = (const float*)d_in[4];
    const float* bout   = (const float*)d_in[5];
    const float* h0     = (const float*)d_in[6];

    cudaFuncSetAttribute(rnn_recurrent,
                         cudaFuncAttributeMaxDynamicSharedMemorySize, SM_TOTAL);

    rnn_xproj<<<(B_ * T_) / 16, 256>>>(inputs, Win, brec);
    rnn_recurrent<<<B_ / 2, 256, SM_TOTAL>>>(Wrec, h0);
    rnn_outproj<<<(B_ * T_) / 64, 256>>>(Wout, bout, (float*)d_out);
}

// round 8
// speedup vs baseline: 1.2173x; 1.2173x over previous
#include <cuda_runtime.h>
#include <cstdint>

#define B_   256
#define T_   512
#define DIN  128
#define H_   512
#define DOUT 64

#define NSTAGE      6
#define CHUNK_K     16
#define CHUNK_BYTES (CHUNK_K * H_ * 4)         // 32768
#define NCHUNK      (H_ / CHUNK_K)             // 32 chunks per step
#define TOTAL_CI    (T_ * NCHUNK)              // 16384

// smem layout (dynamic)
#define SM_W     0                              // 6 x 32KB = 196608
#define SM_HD    (NSTAGE * CHUNK_BYTES)         // 196608 : h dup {h,h} [4][512] float2 = 16384
#define SM_RED   (SM_HD + 4 * H_ * 8)           // 212992 : reduction scratch 256*32B = 8192
#define SM_BAR   (SM_RED + 8192)                // 221184 : full[6] @+0, empty[6] @+48
#define SM_TOTAL (SM_BAR + 128)                 // 221312 (216.1KB < 227KB)

// Scratch (allocation-free rule: __device__ globals)
__device__ float g_xproj[(size_t)B_ * T_ * H_];  // [b][t][h] = inputs@Win + brec
__device__ float g_hall [(size_t)B_ * T_ * H_];  // [b][t][h] = h_t for all t

// Packed fp32x2 FMA
union F2U { float2 f; unsigned long long u; };
__device__ __forceinline__ float2 ffma2(float2 a, float2 b, float2 c) {
    F2U A, Bv, C, D;
    A.f = a; Bv.f = b; C.f = c;
    asm("fma.rn.f32x2 %0, %1, %2, %3;" : "=l"(D.u) : "l"(A.u), "l"(Bv.u), "l"(C.u));
    return D.f;
}

__device__ __forceinline__ uint32_t s2u(const void* p) {
    uint32_t a;
    asm("{ .reg .u64 t; cvta.to.shared.u64 t, %1; cvt.u32.u64 %0, t; }" : "=r"(a) : "l"(p));
    return a;
}
__device__ __forceinline__ void mb_init(uint32_t a, uint32_t cnt) {
    asm volatile("mbarrier.init.shared.b64 [%0], %1;" :: "r"(a), "r"(cnt) : "memory");
}
__device__ __forceinline__ void mb_expect(uint32_t a, uint32_t bytes) {
    asm volatile("mbarrier.arrive.expect_tx.shared.b64 _, [%0], %1;" :: "r"(a), "r"(bytes) : "memory");
}
__device__ __forceinline__ void mb_arrive(uint32_t a) {
    asm volatile("mbarrier.arrive.shared.b64 _, [%0];" :: "r"(a) : "memory");
}
__device__ __forceinline__ void mb_wait(uint32_t a, uint32_t ph) {
    uint32_t done;
    asm volatile("{ .reg .pred p; mbarrier.try_wait.parity.acquire.cta.shared::cta.b64 p, [%1], %2;"
                 "  selp.b32 %0, 1, 0, p; }" : "=r"(done) : "r"(a), "r"(ph) : "memory");
    if (!done) {
        asm volatile("{ .reg .pred P;\n"
                     "WL_%=: mbarrier.try_wait.parity.acquire.cta.shared::cta.b64 P, [%0], %1, 0x989680;\n"
                     " @P bra WD_%=;\n bra WL_%=;\nWD_%=: }" :: "r"(a), "r"(ph) : "memory");
    }
}
__device__ __forceinline__ void bulk_g2s(uint32_t dst, const void* src, uint32_t bytes,
                                         uint32_t mbar) {
    asm volatile("cp.async.bulk.shared::cluster.global.mbarrier::complete_tx::bytes"
                 " [%0], [%1], %2, [%3];"
                 :: "r"(dst), "l"(src), "r"(bytes), "r"(mbar) : "memory");
}

// ---------------------------------------------------------------------------
// Kernel A: xproj = inputs @ Win + brec   (measured 580us)
// ---------------------------------------------------------------------------
__global__ void __launch_bounds__(256) rnn_xproj(
    const float* __restrict__ inputs,
    const float* __restrict__ Win,
    const float* __restrict__ brec)
{
    __shared__ __align__(16) float2 x_dup[16][DIN];
    const int tid = threadIdx.x;
    const size_t r0 = (size_t)blockIdx.x * 16;

    for (int i = tid; i < 16 * DIN; i += 256) {
        int r = i >> 7, k = i & (DIN - 1);
        float v = inputs[(r0 + r) * DIN + k];
        x_dup[r][k] = make_float2(v, v);
    }
    __syncthreads();

    const float2* __restrict__ W2 = reinterpret_cast<const float2*>(Win);
    float2 acc[16];
#pragma unroll
    for (int r = 0; r < 16; r++) acc[r] = make_float2(0.f, 0.f);

#pragma unroll 2
    for (int k = 0; k < DIN; k += 2) {
        float2 w0 = W2[(size_t)k * (H_ / 2) + tid];
        float2 w1 = W2[(size_t)(k + 1) * (H_ / 2) + tid];
#pragma unroll
        for (int r = 0; r < 16; r++) {
            float4 hx = *reinterpret_cast<const float4*>(&x_dup[r][k]);
            acc[r] = ffma2(make_float2(hx.x, hx.y), w0, acc[r]);
            acc[r] = ffma2(make_float2(hx.z, hx.w), w1, acc[r]);
        }
    }

    float2 bb = reinterpret_cast<const float2*>(brec)[tid];
    float2* __restrict__ out2 = reinterpret_cast<float2*>(g_xproj);
#pragma unroll
    for (int r = 0; r < 16; r++)
        out2[(r0 + r) * (H_ / 2) + tid] = make_float2(acc[r].x + bb.x, acc[r].y + bb.y);
}

// ---------------------------------------------------------------------------
// Kernel B: recurrence. 64 CTAs x 4 batch rows, NO clusters, NO cross-CTA
// sync. Wrec streamed per-CTA via 6-stage local cp.async.bulk pipeline.
// Thread (p = warp>>2, q = (warp&3)*32+lane): cols 4q..4q+3, k-parity p.
// full[st]: count 1 (tid0 expect_tx) + 32KB tx. empty[st]: count 8 (lane0s).
// Producer = tid0 (same thread as expecter -> program-order safe).
// ---------------------------------------------------------------------------
extern __shared__ __align__(16) unsigned char sm[];

__global__ void __launch_bounds__(256, 1)
rnn_recurrent(const float* __restrict__ Wrec,
              const float* __restrict__ h0)
{
    const int tid  = threadIdx.x;
    const int lane = tid & 31;
    const int p    = tid >> 7;                 // 0..1 (k-parity / finalize half)
    const int q    = (tid >> 5 & 3) * 32 + lane; // 0..127 (col quad)
    const int c0   = q * 4;
    const int b0   = blockIdx.x * 4;

    const uint32_t smb    = s2u(sm);
    const uint32_t fullb  = smb + SM_BAR;
    const uint32_t emptyb = smb + SM_BAR + 48;

    float2* hd  = reinterpret_cast<float2*>(sm + SM_HD);   // [4][512] {h,h}
    float4* red = reinterpret_cast<float4*>(sm + SM_RED);  // [256][2]

    if (tid == 0)
        for (int s = 0; s < NSTAGE; s++) { mb_init(fullb + 8*s, 1); mb_init(emptyb + 8*s, 8); }

    for (int i = tid; i < H_; i += 256) {      // h = h0 for all 4 rows (dup)
        float v = h0[i];
        float2 vv = make_float2(v, v);
        hd[i] = vv; hd[H_ + i] = vv; hd[2*H_ + i] = vv; hd[3*H_ + i] = vv;
    }
    __syncthreads();

    // Prologue: tid0 arms + issues chunks 0..5. expect precedes TMA in
    // program order of the SAME thread -> no cross-thread ordering needed.
    if (tid == 0) {
        for (int s = 0; s < NSTAGE; s++) {
            mb_expect(fullb + 8*s, CHUNK_BYTES);
            bulk_g2s(smb + SM_W + s * CHUNK_BYTES,
                     Wrec + (size_t)s * CHUNK_K * H_,
                     CHUNK_BYTES, fullb + 8*s);
        }
    }

    int fph[NSTAGE] = {0,0,0,0,0,0};
    int pp [NSTAGE] = {0,0,0,0,0,0};

    const int bf0 = 2 * p, bf1 = 2 * p + 1;        // batches this half finalizes
    const int bo0 = 2 * (1 - p), bo1 = bo0 + 1;    // batches shipped to partner
    float4 xpvA = *reinterpret_cast<const float4*>(
        g_xproj + ((size_t)(b0 + bf0) * T_ + 0) * H_ + c0);
    float4 xpvB = *reinterpret_cast<const float4*>(
        g_xproj + ((size_t)(b0 + bf1) * T_ + 0) * H_ + c0);

    float2 acc[4][2];
#pragma unroll
    for (int b = 0; b < 4; b++) { acc[b][0] = make_float2(0.f,0.f); acc[b][1] = make_float2(0.f,0.f); }

    int st = 0;
    for (int ci = 0; ci < TOTAL_CI; ci++) {
        if (lane == 0) mb_wait(fullb + 8*st, fph[st]);
        fph[st] ^= 1;
        __syncwarp();

        const float4* wb = reinterpret_cast<const float4*>(sm + SM_W + st * CHUNK_BYTES);
        const int hbase = (ci & (NCHUNK - 1)) * (CHUNK_K / 2);  // float4 index
        const float4* h4 = reinterpret_cast<const float4*>(hd);
        int widx = (2 * p) * 128 + q;
#pragma unroll
        for (int j = 0; j < 4; j++) {
            float4 w0 = wb[widx];
            float4 w1 = wb[widx + 128];
            int hj = hbase + 2 * j + p;            // {h[k],h[k],h[k+1],h[k+1]}
#pragma unroll
            for (int b = 0; b < 4; b++) {
                float4 hh = h4[b * 256 + hj];
                acc[b][0] = ffma2(make_float2(hh.x, hh.y), make_float2(w0.x, w0.y), acc[b][0]);
                acc[b][1] = ffma2(make_float2(hh.x, hh.y), make_float2(w0.z, w0.w), acc[b][1]);
                acc[b][0] = ffma2(make_float2(hh.z, hh.w), make_float2(w1.x, w1.y), acc[b][0]);
                acc[b][1] = ffma2(make_float2(hh.z, hh.w), make_float2(w1.z, w1.w), acc[b][1]);
            }
            widx += 512;
        }

        // Re-arm + recycle this stage for chunk ci+6 (all local, cheap).
        const bool more = (ci + NSTAGE) < TOTAL_CI;
        if (tid == 0 && more) mb_expect(fullb + 8*st, CHUNK_BYTES);
        if (lane == 0) mb_arrive(emptyb + 8*st);
        if (tid == 0 && more) {
            mb_wait(emptyb + 8*st, pp[st]); pp[st] ^= 1;
            int nci = ci + NSTAGE;
            bulk_g2s(smb + SM_W + st * CHUNK_BYTES,
                     Wrec + (size_t)(nci & (NCHUNK - 1)) * CHUNK_K * H_,
                     CHUNK_BYTES, fullb + 8*st);
        }

        if ((ci & (NCHUNK - 1)) == (NCHUNK - 1)) {   // ---- step end ----
            int t = ci >> 5;
            // ship partials for the partner's batches (partner = tid ^ 128)
            red[2*tid]     = make_float4(acc[bo0][0].x, acc[bo0][0].y, acc[bo0][1].x, acc[bo0][1].y);
            red[2*tid + 1] = make_float4(acc[bo1][0].x, acc[bo1][0].y, acc[bo1][1].x, acc[bo1][1].y);
            __syncthreads();
            float4 oA = red[2*(tid ^ 128)];
            float4 oB = red[2*(tid ^ 128) + 1];
            float a0 = tanhf(acc[bf0][0].x + oA.x + xpvA.x);
            float a1 = tanhf(acc[bf0][0].y + oA.y + xpvA.y);
            float a2 = tanhf(acc[bf0][1].x + oA.z + xpvA.z);
            float a3 = tanhf(acc[bf0][1].y + oA.w + xpvA.w);
            float b0v = tanhf(acc[bf1][0].x + oB.x + xpvB.x);
            float b1v = tanhf(acc[bf1][0].y + oB.y + xpvB.y);
            float b2v = tanhf(acc[bf1][1].x + oB.z + xpvB.z);
            float b3v = tanhf(acc[bf1][1].y + oB.w + xpvB.w);
            *reinterpret_cast<float4*>(
                g_hall + ((size_t)(b0 + bf0) * T_ + t) * H_ + c0) = make_float4(a0, a1, a2, a3);
            *reinterpret_cast<float4*>(
                g_hall + ((size_t)(b0 + bf1) * T_ + t) * H_ + c0) = make_float4(b0v, b1v, b2v, b3v);
            float4* hA = reinterpret_cast<float4*>(hd + (size_t)bf0 * H_ + c0);
            float4* hB = reinterpret_cast<float4*>(hd + (size_t)bf1 * H_ + c0);
            hA[0] = make_float4(a0, a0, a1, a1);
            hA[1] = make_float4(a2, a2, a3, a3);
            hB[0] = make_float4(b0v, b0v, b1v, b1v);
            hB[1] = make_float4(b2v, b2v, b3v, b3v);
#pragma unroll
            for (int b = 0; b < 4; b++) { acc[b][0] = make_float2(0.f,0.f); acc[b][1] = make_float2(0.f,0.f); }
            if (t + 1 < T_) {
                xpvA = *reinterpret_cast<const float4*>(
                    g_xproj + ((size_t)(b0 + bf0) * T_ + (t + 1)) * H_ + c0);
                xpvB = *reinterpret_cast<const float4*>(
                    g_xproj + ((size_t)(b0 + bf1) * T_ + (t + 1)) * H_ + c0);
            }
            __syncthreads();
        }

        st = (st == NSTAGE - 1) ? 0 : st + 1;
    }
}

// ---------------------------------------------------------------------------
// Kernel C: out = g_hall @ Wout + bout
// ---------------------------------------------------------------------------
__global__ void __launch_bounds__(256, 1) rnn_outproj(
    const float* __restrict__ Wout,
    const float* __restrict__ bout,
    float* __restrict__ out)
{
    __shared__ __align__(16) float2 hdq[64][64];
    const int tid = threadIdx.x;
    const int pair = tid & 31;
    const int rg = tid >> 5;
    const size_t r0 = (size_t)blockIdx.x * 64;

    float2 acc[8];
#pragma unroll
    for (int i = 0; i < 8; i++) acc[i] = make_float2(0.f, 0.f);

    const float2* __restrict__ Wo2 = reinterpret_cast<const float2*>(Wout);

    for (int kc = 0; kc < H_; kc += 64) {
        __syncthreads();
        for (int i = tid; i < 64 * 64; i += 256) {
            int r = i >> 6, k = i & 63;
            float v = g_hall[(r0 + r) * H_ + kc + k];
            hdq[r][k] = make_float2(v, v);
        }
        __syncthreads();

#pragma unroll 4
        for (int kk = 0; kk < 64; kk += 2) {
            float2 w0 = Wo2[(size_t)(kc + kk) * (DOUT / 2) + pair];
            float2 w1 = Wo2[(size_t)(kc + kk + 1) * (DOUT / 2) + pair];
#pragma unroll
            for (int i = 0; i < 8; i++) {
                int r = rg * 8 + i;
                float4 hx = *reinterpret_cast<const float4*>(&hdq[r][kk]);
                acc[i] = ffma2(make_float2(hx.x, hx.y), w0, acc[i]);
                acc[i] = ffma2(make_float2(hx.z, hx.w), w1, acc[i]);
            }
        }
    }

    float2 bb = reinterpret_cast<const float2*>(bout)[pair];
    float2* __restrict__ out2 = reinterpret_cast<float2*>(out);
#pragma unroll
    for (int i = 0; i < 8; i++) {
        int r = rg * 8 + i;
        out2[(r0 + r) * (DOUT / 2) + pair] =
            make_float2(acc[i].x + bb.x, acc[i].y + bb.y);
    }
}

// ---------------------------------------------------------------------------
extern "C" void kernel_launch(void* const* d_in, const int* in_sizes, int n_in,
                              void* d_out, int out_size)
{
    const float* inputs = (const float*)d_in[0];
    const float* Win    = (const float*)d_in[1];
    const float* Wrec   = (const float*)d_in[2];
    const float* brec   = (const float*)d_in[3];
    const float* Wout   = (const float*)d_in[4];
    const float* bout   = (const float*)d_in[5];
    const float* h0     = (const float*)d_in[6];

    cudaFuncSetAttribute(rnn_recurrent,
                         cudaFuncAttributeMaxDynamicSharedMemorySize, SM_TOTAL);

    rnn_xproj<<<(B_ * T_) / 16, 256>>>(inputs, Win, brec);
    rnn_recurrent<<<B_ / 4, 256, SM_TOTAL>>>(Wrec, h0);
    rnn_outproj<<<(B_ * T_) / 64, 256>>>(Wout, bout, (float*)d_out);
}

// round 9
// speedup vs baseline: 2.6124x; 2.1461x over previous
#include <cuda_runtime.h>
#include <cstdint>

#define B_   256
#define T_   512
#define DIN  128
#define H_   512
#define DOUT 64
#define KB   16      // k-rows per register block
#define NBLK 16      // blocks per k-half (256 k)

// Scratch (allocation-free rule: __device__ globals)
__device__ float g_xproj[(size_t)B_ * T_ * H_];  // [b][t][h] = inputs@Win + brec
__device__ float g_hall [(size_t)B_ * T_ * H_];  // [b][t][h] = h_t for all t

// Packed fp32x2 FMA
union F2U { float2 f; unsigned long long u; };
__device__ __forceinline__ float2 ffma2(float2 a, float2 b, float2 c) {
    F2U A, Bv, C, D;
    A.f = a; Bv.f = b; C.f = c;
    asm("fma.rn.f32x2 %0, %1, %2, %3;" : "=l"(D.u) : "l"(A.u), "l"(Bv.u), "l"(C.u));
    return D.f;
}

// ---------------------------------------------------------------------------
// Kernel A: xproj = inputs @ Win + brec   (measured 584us)
// ---------------------------------------------------------------------------
__global__ void __launch_bounds__(256) rnn_xproj(
    const float* __restrict__ inputs,
    const float* __restrict__ Win,
    const float* __restrict__ brec)
{
    __shared__ __align__(16) float2 x_dup[16][DIN];
    const int tid = threadIdx.x;
    const size_t r0 = (size_t)blockIdx.x * 16;

    for (int i = tid; i < 16 * DIN; i += 256) {
        int r = i >> 7, k = i & (DIN - 1);
        float v = inputs[(r0 + r) * DIN + k];
        x_dup[r][k] = make_float2(v, v);
    }
    __syncthreads();

    const float2* __restrict__ W2 = reinterpret_cast<const float2*>(Win);
    float2 acc[16];
#pragma unroll
    for (int r = 0; r < 16; r++) acc[r] = make_float2(0.f, 0.f);

#pragma unroll 2
    for (int k = 0; k < DIN; k += 2) {
        float2 w0 = W2[(size_t)k * (H_ / 2) + tid];
        float2 w1 = W2[(size_t)(k + 1) * (H_ / 2) + tid];
#pragma unroll
        for (int r = 0; r < 16; r++) {
            float4 hx = *reinterpret_cast<const float4*>(&x_dup[r][k]);
            acc[r] = ffma2(make_float2(hx.x, hx.y), w0, acc[r]);
            acc[r] = ffma2(make_float2(hx.z, hx.w), w1, acc[r]);
        }
    }

    float2 bb = reinterpret_cast<const float2*>(brec)[tid];
    float2* __restrict__ out2 = reinterpret_cast<float2*>(g_xproj);
#pragma unroll
    for (int r = 0; r < 16; r++)
        out2[(r0 + r) * (H_ / 2) + tid] = make_float2(acc[r].x + bb.x, acc[r].y + bb.y);
}

// ---------------------------------------------------------------------------
// Kernel B: recurrence. 64 CTAs x 4 batch rows. NO clusters, NO mbarriers,
// NO per-chunk sync. W streamed straight to registers (LDG.128, double-
// buffered 16-k blocks). k split 2-ways across warp halves; h = {h,h} SMEM
// broadcast, double-buffered; one partial-exchange + 2 syncthreads per STEP.
// Thread: p = warp>>2 (k-half), q = (warp&3)*32+lane -> cols 4q..4q+3.
// ---------------------------------------------------------------------------
__global__ void __launch_bounds__(256, 1)
rnn_recurrent(const float* __restrict__ Wrec,
              const float* __restrict__ h0)
{
    __shared__ __align__(16) float2 hdup[2][4][H_];  // {h,h} dup, 32KB
    __shared__ __align__(16) float4 red[256][2];     // step-end exchange, 8KB

    const int tid  = threadIdx.x;
    const int lane = tid & 31, warp = tid >> 5;
    const int p    = warp >> 2;                // k-half
    const int q    = (warp & 3) * 32 + lane;   // col-quad
    const int c0   = 4 * q;
    const int k0   = p * 256;
    const int b0   = blockIdx.x * 4;
    const int bf0  = 2 * p,       bf1 = bf0 + 1;   // batches this half finalizes
    const int bo0  = 2 - 2 * p,   bo1 = bo0 + 1;   // batches shipped to partner

    for (int i = tid; i < 4 * H_; i += 256) {  // h = h0 for all 4 rows (dup)
        int b = i >> 9, k = i & 511;
        float v = h0[k];
        hdup[0][b][k] = make_float2(v, v);
    }
    __syncthreads();

    const float* wbase = Wrec + c0;
    float4 wb0[KB], wb1[KB];

    // prologue: block 0 of my k-half
#pragma unroll
    for (int kk = 0; kk < KB; kk++)
        wb0[kk] = __ldg(reinterpret_cast<const float4*>(wbase + (size_t)(k0 + kk) * H_));

    float4 xpA = *reinterpret_cast<const float4*>(
        g_xproj + ((size_t)(b0 + bf0) * T_) * H_ + c0);
    float4 xpB = *reinterpret_cast<const float4*>(
        g_xproj + ((size_t)(b0 + bf1) * T_) * H_ + c0);

    float2 acc[4][2];
#pragma unroll
    for (int b = 0; b < 4; b++) { acc[b][0] = make_float2(0.f,0.f); acc[b][1] = make_float2(0.f,0.f); }

    int hb = 0;
    for (int t = 0; t < T_; t++) {
#pragma unroll 1
        for (int bb = 0; bb < NBLK / 2; bb++) {
            const int blk0 = 2 * bb, blk1 = 2 * bb + 1;

            // prefetch blk1 -> wb1, compute blk0 from wb0
#pragma unroll
            for (int kk = 0; kk < KB; kk++)
                wb1[kk] = __ldg(reinterpret_cast<const float4*>(
                    wbase + (size_t)(k0 + blk1 * KB + kk) * H_));
            {
                const int kb = k0 + blk0 * KB;
#pragma unroll
                for (int kk = 0; kk < KB; kk += 2) {
                    float4 w0 = wb0[kk], w1 = wb0[kk + 1];
#pragma unroll
                    for (int b = 0; b < 4; b++) {
                        float4 hh = *reinterpret_cast<const float4*>(&hdup[hb][b][kb + kk]);
                        acc[b][0] = ffma2(make_float2(hh.x, hh.y), make_float2(w0.x, w0.y), acc[b][0]);
                        acc[b][1] = ffma2(make_float2(hh.x, hh.y), make_float2(w0.z, w0.w), acc[b][1]);
                        acc[b][0] = ffma2(make_float2(hh.z, hh.w), make_float2(w1.x, w1.y), acc[b][0]);
                        acc[b][1] = ffma2(make_float2(hh.z, hh.w), make_float2(w1.z, w1.w), acc[b][1]);
                    }
                }
            }

            // prefetch blk0+2 (wraps to block 0 for next step) -> wb0, compute blk1 from wb1
            const int nblk = (blk1 + 1) & (NBLK - 1);
#pragma unroll
            for (int kk = 0; kk < KB; kk++)
                wb0[kk] = __ldg(reinterpret_cast<const float4*>(
                    wbase + (size_t)(k0 + nblk * KB + kk) * H_));
            {
                const int kb = k0 + blk1 * KB;
#pragma unroll
                for (int kk = 0; kk < KB; kk += 2) {
                    float4 w0 = wb1[kk], w1 = wb1[kk + 1];
#pragma unroll
                    for (int b = 0; b < 4; b++) {
                        float4 hh = *reinterpret_cast<const float4*>(&hdup[hb][b][kb + kk]);
                        acc[b][0] = ffma2(make_float2(hh.x, hh.y), make_float2(w0.x, w0.y), acc[b][0]);
                        acc[b][1] = ffma2(make_float2(hh.x, hh.y), make_float2(w0.z, w0.w), acc[b][1]);
                        acc[b][0] = ffma2(make_float2(hh.z, hh.w), make_float2(w1.x, w1.y), acc[b][0]);
                        acc[b][1] = ffma2(make_float2(hh.z, hh.w), make_float2(w1.z, w1.w), acc[b][1]);
                    }
                }
            }
        }

        // ---- step end: exchange partner-half partials, tanh, h update ----
        red[tid][0] = make_float4(acc[bo0][0].x, acc[bo0][0].y, acc[bo0][1].x, acc[bo0][1].y);
        red[tid][1] = make_float4(acc[bo1][0].x, acc[bo1][0].y, acc[bo1][1].x, acc[bo1][1].y);
        __syncthreads();
        float4 oA = red[tid ^ 128][0];
        float4 oB = red[tid ^ 128][1];

        float a0 = tanhf(acc[bf0][0].x + oA.x + xpA.x);
        float a1 = tanhf(acc[bf0][0].y + oA.y + xpA.y);
        float a2 = tanhf(acc[bf0][1].x + oA.z + xpA.z);
        float a3 = tanhf(acc[bf0][1].y + oA.w + xpA.w);
        float e0 = tanhf(acc[bf1][0].x + oB.x + xpB.x);
        float e1 = tanhf(acc[bf1][0].y + oB.y + xpB.y);
        float e2 = tanhf(acc[bf1][1].x + oB.z + xpB.z);
        float e3 = tanhf(acc[bf1][1].y + oB.w + xpB.w);

        *reinterpret_cast<float4*>(
            g_hall + ((size_t)(b0 + bf0) * T_ + t) * H_ + c0) = make_float4(a0, a1, a2, a3);
        *reinterpret_cast<float4*>(
            g_hall + ((size_t)(b0 + bf1) * T_ + t) * H_ + c0) = make_float4(e0, e1, e2, e3);

        float4* hA = reinterpret_cast<float4*>(&hdup[hb ^ 1][bf0][c0]);
        hA[0] = make_float4(a0, a0, a1, a1);
        hA[1] = make_float4(a2, a2, a3, a3);
        float4* hBp = reinterpret_cast<float4*>(&hdup[hb ^ 1][bf1][c0]);
        hBp[0] = make_float4(e0, e0, e1, e1);
        hBp[1] = make_float4(e2, e2, e3, e3);

#pragma unroll
        for (int b = 0; b < 4; b++) { acc[b][0] = make_float2(0.f,0.f); acc[b][1] = make_float2(0.f,0.f); }
        if (t + 1 < T_) {
            xpA = *reinterpret_cast<const float4*>(
                g_xproj + ((size_t)(b0 + bf0) * T_ + (t + 1)) * H_ + c0);
            xpB = *reinterpret_cast<const float4*>(
                g_xproj + ((size_t)(b0 + bf1) * T_ + (t + 1)) * H_ + c0);
        }
        __syncthreads();
        hb ^= 1;
    }
}

// ---------------------------------------------------------------------------
// Kernel C: out = g_hall @ Wout + bout
// ---------------------------------------------------------------------------
__global__ void __launch_bounds__(256, 1) rnn_outproj(
    const float* __restrict__ Wout,
    const float* __restrict__ bout,
    float* __restrict__ out)
{
    __shared__ __align__(16) float2 hdq[64][64];
    const int tid = threadIdx.x;
    const int pair = tid & 31;
    const int rg = tid >> 5;
    const size_t r0 = (size_t)blockIdx.x * 64;

    float2 acc[8];
#pragma unroll
    for (int i = 0; i < 8; i++) acc[i] = make_float2(0.f, 0.f);

    const float2* __restrict__ Wo2 = reinterpret_cast<const float2*>(Wout);

    for (int kc = 0; kc < H_; kc += 64) {
        __syncthreads();
        for (int i = tid; i < 64 * 64; i += 256) {
            int r = i >> 6, k = i & 63;
            float v = g_hall[(r0 + r) * H_ + kc + k];
            hdq[r][k] = make_float2(v, v);
        }
        __syncthreads();

#pragma unroll 4
        for (int kk = 0; kk < 64; kk += 2) {
            float2 w0 = Wo2[(size_t)(kc + kk) * (DOUT / 2) + pair];
            float2 w1 = Wo2[(size_t)(kc + kk + 1) * (DOUT / 2) + pair];
#pragma unroll
            for (int i = 0; i < 8; i++) {
                int r = rg * 8 + i;
                float4 hx = *reinterpret_cast<const float4*>(&hdq[r][kk]);
                acc[i] = ffma2(make_float2(hx.x, hx.y), w0, acc[i]);
                acc[i] = ffma2(make_float2(hx.z, hx.w), w1, acc[i]);
            }
        }
    }

    float2 bb = reinterpret_cast<const float2*>(bout)[pair];
    float2* __restrict__ out2 = reinterpret_cast<float2*>(out);
#pragma unroll
    for (int i = 0; i < 8; i++) {
        int r = rg * 8 + i;
        out2[(r0 + r) * (DOUT / 2) + pair] =
            make_float2(acc[i].x + bb.x, acc[i].y + bb.y);
    }
}

// ---------------------------------------------------------------------------
extern "C" void kernel_launch(void* const* d_in, const int* in_sizes, int n_in,
                              void* d_out, int out_size)
{
    const float* inputs = (const float*)d_in[0];
    const float* Win    = (const float*)d_in[1];
    const float* Wrec   = (const float*)d_in[2];
    const float* brec   = (const float*)d_in[3];
    const float* Wout   = (const float*)d_in[4];
    const float* bout   = (const float*)d_in[5];
    const float* h0     = (const float*)d_in[6];

    rnn_xproj<<<(B_ * T_) / 16, 256>>>(inputs, Win, brec);
    rnn_recurrent<<<B_ / 4, 256>>>(Wrec, h0);
    rnn_outproj<<<(B_ * T_) / 64, 256>>>(Wout, bout, (float*)d_out);
}